// round 7
// baseline (speedup 1.0000x reference)
#include <cuda_runtime.h>
#include <cstdint>

// LSTM_1279900254644: 2-layer LSTM, B=512, L=1000, H=128.
// Cluster-of-4 design: each CTA keeps the weight rows of its 32 h-dims
// (all gates, all 3 matrices, full K) resident in SMEM (192KB). Per-step
// h-state exchange via DSMEM (mapa + st.shared::cluster), 2 cluster syncs/step.

#define B_DIM 512
#define L_DIM 1000
#define H_DIM 128
#define MB    15            // batches per cluster
#define NCL   36            // clusters (36*15 = 540 >= 512; fits one wave on either die split)
#define NBLK  (NCL * 4)
#define BLK_T 512
#define WSTRIDE 130         // ull2 slots per k4-row (128 rl + 2 pad -> bank-conflict-free)
#define W_BYTES (96 * WSTRIDE * 16)   // 3 mats * 32 k4 * 130 * 16B = 199,680
#define SMEM_BYTES (W_BYTES + (2*MB*128 + MB*128 + MB*128 + 2*MB + 4*MB) * 4)

// Packed weights, per-CTA order: [rank 4][mat 3][k4 32][rl 128] as 16B chunks.
__device__ ulonglong2 g_wpack[4 * 96 * 128];

typedef unsigned long long ull;

__device__ __forceinline__ void ffma2(ull& d, ull a, ull b) {
    asm("fma.rn.f32x2 %0, %1, %2, %0;" : "+l"(d) : "l"(a), "l"(b));
}
__device__ __forceinline__ float pksum(ull v) {
    float a, b;
    asm("mov.b64 {%0,%1}, %2;" : "=f"(a), "=f"(b) : "l"(v));
    return a + b;
}
__device__ __forceinline__ float sigf(float x) {
    return __fdividef(1.f, 1.f + __expf(-x));
}
__device__ __forceinline__ float tanh_fast(float x) {
    return 1.f - __fdividef(2.f, __expf(2.f * x) + 1.f);
}
__device__ __forceinline__ uint32_t smem_u32(const void* p) {
    uint32_t a;
    asm("{ .reg .u64 t; cvta.to.shared.u64 t, %1; cvt.u32.u64 %0, t; }" : "=r"(a) : "l"(p));
    return a;
}
__device__ __forceinline__ void cluster_sync() {
    asm volatile("barrier.cluster.arrive.aligned;" ::: "memory");
    asm volatile("barrier.cluster.wait.aligned;" ::: "memory");
}
// Store one float to the same SMEM offset in all 4 cluster CTAs.
__device__ __forceinline__ void push_all(uint32_t laddr, float v) {
    #pragma unroll
    for (int r = 0; r < 4; ++r) {
        uint32_t ra;
        asm volatile("mapa.shared::cluster.u32 %0, %1, %2;" : "=r"(ra) : "r"(laddr), "r"(r));
        asm volatile("st.shared::cluster.f32 [%0], %1;" :: "r"(ra), "f"(v) : "memory");
    }
}
__device__ __forceinline__ void push_rank0(uint32_t laddr, float v) {
    uint32_t ra;
    asm volatile("mapa.shared::cluster.u32 %0, %1, %2;" : "=r"(ra) : "r"(laddr), "r"(0));
    asm volatile("st.shared::cluster.f32 [%0], %1;" :: "r"(ra), "f"(v) : "memory");
}

__global__ void pack_weights(const float* __restrict__ w1,
                             const float* __restrict__ w2i,
                             const float* __restrict__ w2h) {
    int idx = blockIdx.x * blockDim.x + threadIdx.x;   // [rank][mk][rl]
    if (idx >= 4 * 96 * 128) return;
    int rl   = idx & 127;
    int mk   = (idx >> 7) % 96;
    int rank = idx / (96 * 128);
    int mat = mk / 32, k4 = mk % 32;
    int row = ((rl >> 5) << 7) + (rank << 5) + (rl & 31);   // 128*gate + 32*rank + dim
    const float* src = (mat == 0) ? w1 : (mat == 1) ? w2i : w2h;
    const float* s = src + row * H_DIM + 4 * k4;
    ull lo = ((ull)__float_as_uint(s[1]) << 32) | __float_as_uint(s[0]);
    ull hi = ((ull)__float_as_uint(s[3]) << 32) | __float_as_uint(s[2]);
    ulonglong2 v; v.x = lo; v.y = hi;
    g_wpack[idx] = v;
}

__global__ __launch_bounds__(BLK_T, 1) __cluster_dims__(4, 1, 1)
void lstm_main(const float* __restrict__ y,
               const float* __restrict__ Wih1,
               const float* __restrict__ bih1,
               const float* __restrict__ bhh1,
               const float* __restrict__ bih2,
               const float* __restrict__ bhh2,
               const float* __restrict__ Wlin,
               const float* __restrict__ blin,
               float* __restrict__ out) {
    extern __shared__ unsigned char smem_raw[];
    const int tid = threadIdx.x;
    uint32_t rank;
    asm("mov.u32 %0, %%cluster_ctarank;" : "=r"(rank));
    const int cl    = blockIdx.x >> 2;
    const int bbase = cl * MB;

    // ---- SMEM layout ----
    ulonglong2*  Wsm = (ulonglong2*)smem_raw;                     // [3*32][130] (16B units)
    float* h1s = (float*)(smem_raw + W_BYTES);                    // [2][MB][128]
    float* h2s = h1s + 2 * MB * 128;                              // [MB][128]
    float* gsm = h2s + MB * 128;                                  // [MB][128]
    float* xs  = gsm + MB * 128;                                  // [2][MB]
    float* outp = xs + 2 * MB;                                    // [4][MB]

    const uint32_t h1_u32 = smem_u32(h1s);
    const uint32_t h2_u32 = smem_u32(h2s);
    const uint32_t op_u32 = smem_u32(outp);

    // ---- thread roles ----
    const int rl = tid >> 2;          // local row 0..127
    const int kq = tid & 3;           // interleaved K-quarter (k4 = 4i + kq)
    const int grow = ((rl >> 5) << 7) + ((int)rank << 5) + (rl & 31);  // global gate row
    const int m_c = tid >> 5;         // cell role: batch index
    const int d_c = tid & 31;         // cell role: local dim
    const bool is_cell = (tid < MB * 32);

    const float wih1_r = Wih1[grow];
    const float b1_r   = bih1[grow] + bhh1[grow];
    const float b2_r   = bih2[grow] + bhh2[grow];
    const float wlin_d = Wlin[((int)rank << 5) + d_c];
    const float blin0  = blin[0];

    // ---- init: zero h-state, load weights into SMEM ----
    for (int i = tid; i < 3 * MB * 128; i += BLK_T) h1s[i] = 0.f;   // h1s(both) + h2s
    for (int i = tid; i < 96 * 128; i += BLK_T) {
        int mk = i >> 7, r = i & 127;
        Wsm[mk * WSTRIDE + r] = g_wpack[((int)rank * 96 + mk) * 128 + i % 128 - (i & 127) + r]; // = g_wpack[rank*96*128 + i]
    }
    if (tid < MB) {
        int b = bbase + tid;
        xs[tid] = (b < B_DIM) ? y[b * L_DIM] : 0.f;
    }
    __syncthreads();
    cluster_sync();   // everyone's zeros + weights ready before any remote pushes

    float c1 = 0.f, c2 = 0.f, h2n = 0.f;
    int p = 0;

    for (int t = 0; t < L_DIM; ++t) {
        // ---- phase 0: publish h2 (from previous step's D; zeros at t=0) ----
        if (is_cell) {
            uint32_t a = h2_u32 + (((m_c << 7) + ((int)rank << 5) + d_c) << 2);
            push_all(a, h2n);
        }

        // ---- stage A: layer-1 gates over h1[p] ----
        ull acc[MB];
        #pragma unroll
        for (int m = 0; m < MB; ++m) acc[m] = 0ULL;
        {
            const ulonglong2* hA = (const ulonglong2*)(h1s + p * MB * 128);
            #pragma unroll
            for (int i = 0; i < 8; ++i) {
                int k4 = (i << 2) + kq;
                ulonglong2 w = Wsm[k4 * WSTRIDE + rl];
                #pragma unroll
                for (int m = 0; m < MB; ++m) {
                    ulonglong2 h = hA[m * 32 + k4];
                    ffma2(acc[m], w.x, h.x);
                    ffma2(acc[m], w.y, h.y);
                }
            }
        }
        #pragma unroll
        for (int m = 0; m < MB; ++m) {
            float s = pksum(acc[m]);
            s += __shfl_xor_sync(0xffffffffu, s, 1);
            s += __shfl_xor_sync(0xffffffffu, s, 2);
            if (kq == 0)
                gsm[m * 128 + rl] = fmaf(xs[p * MB + m], wih1_r, b1_r) + s;
        }
        __syncthreads();

        // ---- stage B: layer-1 cell update -> h1[p^1] everywhere ----
        if (is_cell) {
            const float* g = gsm + m_c * 128;
            float ii = sigf(g[d_c]);
            float ff = sigf(g[32 + d_c]);
            float gg = tanh_fast(g[64 + d_c]);
            float oo = sigf(g[96 + d_c]);
            c1 = ff * c1 + ii * gg;
            float h1n = oo * tanh_fast(c1);
            uint32_t a = h1_u32 +
                ((((p ^ 1) * MB * 128) + (m_c << 7) + ((int)rank << 5) + d_c) << 2);
            push_all(a, h1n);
        } else if (tid >= MB * 32 && tid < MB * 32 + MB) {
            int m = tid - MB * 32;
            int b = bbase + m;
            xs[(p ^ 1) * MB + m] =
                (b < B_DIM && t + 1 < L_DIM) ? y[b * L_DIM + t + 1] : 0.f;
        }
        cluster_sync();   // h1[p^1] + h2 visible cluster-wide

        // ---- stage C: layer-2 gates over h1[p^1] and h2 ----
        #pragma unroll
        for (int m = 0; m < MB; ++m) acc[m] = 0ULL;
        {
            const ulonglong2* hA = (const ulonglong2*)(h1s + (p ^ 1) * MB * 128);
            const ulonglong2* hB = (const ulonglong2*)h2s;
            #pragma unroll
            for (int i = 0; i < 8; ++i) {
                int k4 = (i << 2) + kq;
                ulonglong2 wi = Wsm[(32 + k4) * WSTRIDE + rl];
                ulonglong2 wh = Wsm[(64 + k4) * WSTRIDE + rl];
                #pragma unroll
                for (int m = 0; m < MB; ++m) {
                    ulonglong2 ha = hA[m * 32 + k4];
                    ulonglong2 hb = hB[m * 32 + k4];
                    ffma2(acc[m], wi.x, ha.x);
                    ffma2(acc[m], wi.y, ha.y);
                    ffma2(acc[m], wh.x, hb.x);
                    ffma2(acc[m], wh.y, hb.y);
                }
            }
        }
        #pragma unroll
        for (int m = 0; m < MB; ++m) {
            float s = pksum(acc[m]);
            s += __shfl_xor_sync(0xffffffffu, s, 1);
            s += __shfl_xor_sync(0xffffffffu, s, 2);
            if (kq == 0)
                gsm[m * 128 + rl] = s + b2_r;
        }
        __syncthreads();

        // ---- stage D: layer-2 cell update + output partial ----
        if (is_cell) {
            const float* g = gsm + m_c * 128;
            float ii = sigf(g[d_c]);
            float ff = sigf(g[32 + d_c]);
            float gg = tanh_fast(g[64 + d_c]);
            float oo = sigf(g[96 + d_c]);
            c2 = ff * c2 + ii * gg;
            h2n = oo * tanh_fast(c2);       // published at next step's phase 0
            float op = h2n * wlin_d;
            #pragma unroll
            for (int off = 16; off > 0; off >>= 1)
                op += __shfl_xor_sync(0xffffffffu, op, off);
            if (d_c == 0)
                push_rank0(op_u32 + ((((int)rank) * MB + m_c) << 2), op);
        }
        cluster_sync();   // outp visible on rank 0; h-buffers safe to rotate

        // ---- stage E: rank-0 writes the scalar outputs ----
        if (rank == 0 && tid < MB) {
            int b = bbase + tid;
            if (b < B_DIM)
                out[b * L_DIM + t] = outp[tid] + outp[MB + tid] +
                                     outp[2 * MB + tid] + outp[3 * MB + tid] + blin0;
        }
        p ^= 1;
    }
}

extern "C" void kernel_launch(void* const* d_in, const int* in_sizes, int n_in,
                              void* d_out, int out_size) {
    const float* y    = (const float*)d_in[0];
    const float* Wih1 = (const float*)d_in[1];
    const float* Whh1 = (const float*)d_in[2];
    const float* bih1 = (const float*)d_in[3];
    const float* bhh1 = (const float*)d_in[4];
    const float* Wih2 = (const float*)d_in[5];
    const float* Whh2 = (const float*)d_in[6];
    const float* bih2 = (const float*)d_in[7];
    const float* bhh2 = (const float*)d_in[8];
    const float* Wlin = (const float*)d_in[9];
    const float* blin = (const float*)d_in[10];
    float* out = (float*)d_out;

    cudaFuncSetAttribute(lstm_main, cudaFuncAttributeMaxDynamicSharedMemorySize,
                         SMEM_BYTES);

    pack_weights<<<(4 * 96 * 128 + 255) / 256, 256>>>(Whh1, Wih2, Whh2);
    lstm_main<<<NBLK, BLK_T, SMEM_BYTES>>>(y, Wih1, bih1, bhh1, bih2, bhh2,
                                           Wlin, blin, out);
}

// round 8
// speedup vs baseline: 1.3966x; 1.3966x over previous
#include <cuda_runtime.h>
#include <cstdint>

// LSTM_1279900254644: 2-layer LSTM, B=512, L=1000, H=128.
// Cluster-of-4, weights SMEM-resident (each CTA: rows of its 32 h-dims x 4 gates
// for all 3 matrices). Round fixes: 32 clusters (128 CTAs <= 132 co-resident for
// cluster4 -> ONE wave), and kq8/2-row thread mapping (full-wavefront h loads).

#define B_DIM 512
#define L_DIM 1000
#define H_DIM 128
#define MB    16            // batches per cluster; 32*16 = 512 exactly
#define NCL   32
#define NBLK  (NCL * 4)
#define BLK_T 512
#define WSTRIDE 129         // ull2 slots per k4-row; 129 % 8 == 1 -> perfect chunk spread
#define W_BYTES (96 * WSTRIDE * 16)   // 198144
#define SMEM_BYTES (W_BYTES + (2*MB*128 + MB*128 + MB*128 + 2*MB + 4*MB) * 4) // 231296

// Packed weights, per-CTA order: [rank 4][mat 3][k4 32][rl 128] as 16B chunks.
__device__ ulonglong2 g_wpack[4 * 96 * 128];

typedef unsigned long long ull;

__device__ __forceinline__ void ffma2(ull& d, ull a, ull b) {
    asm("fma.rn.f32x2 %0, %1, %2, %0;" : "+l"(d) : "l"(a), "l"(b));
}
__device__ __forceinline__ float pksum(ull v) {
    float a, b;
    asm("mov.b64 {%0,%1}, %2;" : "=f"(a), "=f"(b) : "l"(v));
    return a + b;
}
__device__ __forceinline__ float sigf(float x) {
    return __fdividef(1.f, 1.f + __expf(-x));
}
__device__ __forceinline__ float tanh_fast(float x) {
    return 1.f - __fdividef(2.f, __expf(2.f * x) + 1.f);
}
__device__ __forceinline__ uint32_t smem_u32(const void* p) {
    uint32_t a;
    asm("{ .reg .u64 t; cvta.to.shared.u64 t, %1; cvt.u32.u64 %0, t; }" : "=r"(a) : "l"(p));
    return a;
}
__device__ __forceinline__ void cluster_sync() {
    asm volatile("barrier.cluster.arrive.aligned;" ::: "memory");
    asm volatile("barrier.cluster.wait.aligned;" ::: "memory");
}
__device__ __forceinline__ void push_all(uint32_t laddr, float v) {
    #pragma unroll
    for (int r = 0; r < 4; ++r) {
        uint32_t ra;
        asm volatile("mapa.shared::cluster.u32 %0, %1, %2;" : "=r"(ra) : "r"(laddr), "r"(r));
        asm volatile("st.shared::cluster.f32 [%0], %1;" :: "r"(ra), "f"(v) : "memory");
    }
}
__device__ __forceinline__ void push_rank0(uint32_t laddr, float v) {
    uint32_t ra;
    asm volatile("mapa.shared::cluster.u32 %0, %1, %2;" : "=r"(ra) : "r"(laddr), "r"(0));
    asm volatile("st.shared::cluster.f32 [%0], %1;" :: "r"(ra), "f"(v) : "memory");
}

__global__ void pack_weights(const float* __restrict__ w1,
                             const float* __restrict__ w2i,
                             const float* __restrict__ w2h) {
    int idx = blockIdx.x * blockDim.x + threadIdx.x;   // [rank][mk][rl]
    if (idx >= 4 * 96 * 128) return;
    int rl   = idx & 127;
    int mk   = (idx >> 7) % 96;
    int rank = idx / (96 * 128);
    int mat = mk / 32, k4 = mk % 32;
    int row = ((rl >> 5) << 7) + (rank << 5) + (rl & 31);   // 128*gate + 32*rank + dim
    const float* src = (mat == 0) ? w1 : (mat == 1) ? w2i : w2h;
    const float* s = src + row * H_DIM + 4 * k4;
    ull lo = ((ull)__float_as_uint(s[1]) << 32) | __float_as_uint(s[0]);
    ull hi = ((ull)__float_as_uint(s[3]) << 32) | __float_as_uint(s[2]);
    ulonglong2 v; v.x = lo; v.y = hi;
    g_wpack[idx] = v;
}

__global__ __launch_bounds__(BLK_T, 1) __cluster_dims__(4, 1, 1)
void lstm_main(const float* __restrict__ y,
               const float* __restrict__ Wih1,
               const float* __restrict__ bih1,
               const float* __restrict__ bhh1,
               const float* __restrict__ bih2,
               const float* __restrict__ bhh2,
               const float* __restrict__ Wlin,
               const float* __restrict__ blin,
               float* __restrict__ out) {
    extern __shared__ unsigned char smem_raw[];
    const int tid = threadIdx.x;
    uint32_t rank;
    asm("mov.u32 %0, %%cluster_ctarank;" : "=r"(rank));
    const int cl    = blockIdx.x >> 2;
    const int bbase = cl * MB;

    // ---- SMEM layout ----
    ulonglong2* Wsm = (ulonglong2*)smem_raw;                      // [3*32][129] 16B units
    float* h1s = (float*)(smem_raw + W_BYTES);                    // [2][MB][128]
    float* h2s = h1s + 2 * MB * 128;                              // [MB][128]
    float* gsm = h2s + MB * 128;                                  // [MB][128]
    float* xs  = gsm + MB * 128;                                  // [2][MB]
    float* outp = xs + 2 * MB;                                    // [4][MB]

    const uint32_t h1_u32 = smem_u32(h1s);
    const uint32_t h2_u32 = smem_u32(h2s);
    const uint32_t op_u32 = smem_u32(outp);

    // ---- thread roles ----
    const int rl = tid >> 3;          // local row pair base: rows rl and rl+64
    const int kq = tid & 7;           // K-eighth: k4 = 8*i + kq
    const int m_c = tid >> 5;         // cell role: batch (MB*32 == 512 -> all threads)
    const int d_c = tid & 31;         // cell role: local dim

    // global gate rows for this thread's two local rows (rA=rl in gates 0..1, rB=rl+64)
    const int growA = ((rl >> 5) << 7) + ((int)rank << 5) + (rl & 31);
    const int rB = rl + 64;
    const int growB = ((rB >> 5) << 7) + ((int)rank << 5) + (rB & 31);

    const float wih1A = Wih1[growA], wih1B = Wih1[growB];
    const float b1A = bih1[growA] + bhh1[growA];
    const float b1B = bih1[growB] + bhh1[growB];
    const float b2A = bih2[growA] + bhh2[growA];
    const float b2B = bih2[growB] + bhh2[growB];
    const float wlin_d = Wlin[((int)rank << 5) + d_c];
    const float blin0  = blin[0];

    // ---- init: zero h-state (h1 both buffers + h2), load weights ----
    for (int i = tid; i < 3 * MB * 128; i += BLK_T) h1s[i] = 0.f;
    for (int i = tid; i < 96 * 128; i += BLK_T) {
        int mk = i >> 7, r = i & 127;
        Wsm[mk * WSTRIDE + r] = g_wpack[(int)rank * 96 * 128 + i];
    }
    if (tid < MB) {
        int b = bbase + tid;
        xs[tid] = (b < B_DIM) ? y[b * L_DIM] : 0.f;
    }
    __syncthreads();
    cluster_sync();

    float c1 = 0.f, c2 = 0.f, h2n = 0.f;
    int p = 0;

    for (int t = 0; t < L_DIM; ++t) {
        // ---- phase 0: publish h2 from previous step (zeros at t=0) ----
        push_all(h2_u32 + (((m_c << 7) + ((int)rank << 5) + d_c) << 2), h2n);

        // ---- stage A: layer-1 gates over h1[p] ----
        {
            const ulonglong2* hA = (const ulonglong2*)(h1s + p * MB * 128);
            #pragma unroll
            for (int half = 0; half < 2; ++half) {
                ull accA[8], accB[8];
                #pragma unroll
                for (int m = 0; m < 8; ++m) { accA[m] = 0ULL; accB[m] = 0ULL; }
                #pragma unroll
                for (int i = 0; i < 4; ++i) {
                    int k4 = (i << 3) + kq;
                    ulonglong2 wA = Wsm[k4 * WSTRIDE + rl];
                    ulonglong2 wB = Wsm[k4 * WSTRIDE + rB];
                    #pragma unroll
                    for (int m = 0; m < 8; ++m) {
                        ulonglong2 h = hA[((half << 3) + m) * 32 + k4];
                        ffma2(accA[m], wA.x, h.x); ffma2(accA[m], wA.y, h.y);
                        ffma2(accB[m], wB.x, h.x); ffma2(accB[m], wB.y, h.y);
                    }
                }
                #pragma unroll
                for (int m = 0; m < 8; ++m) {
                    int mm = (half << 3) + m;
                    float sA = pksum(accA[m]);
                    float sB = pksum(accB[m]);
                    sA += __shfl_xor_sync(0xffffffffu, sA, 1);
                    sA += __shfl_xor_sync(0xffffffffu, sA, 2);
                    sA += __shfl_xor_sync(0xffffffffu, sA, 4);
                    sB += __shfl_xor_sync(0xffffffffu, sB, 1);
                    sB += __shfl_xor_sync(0xffffffffu, sB, 2);
                    sB += __shfl_xor_sync(0xffffffffu, sB, 4);
                    if (kq == 0) {
                        float x = xs[p * MB + mm];
                        gsm[mm * 128 + rl] = fmaf(x, wih1A, b1A) + sA;
                        gsm[mm * 128 + rB] = fmaf(x, wih1B, b1B) + sB;
                    }
                }
            }
        }
        __syncthreads();

        // ---- stage B: layer-1 cell update -> h1[p^1] on all 4 CTAs ----
        {
            const float* g = gsm + (m_c << 7);
            float ii = sigf(g[d_c]);
            float ff = sigf(g[32 + d_c]);
            float gg = tanh_fast(g[64 + d_c]);
            float oo = sigf(g[96 + d_c]);
            c1 = ff * c1 + ii * gg;
            float h1n = oo * tanh_fast(c1);
            push_all(h1_u32 +
                ((((p ^ 1) * MB * 128) + (m_c << 7) + ((int)rank << 5) + d_c) << 2), h1n);
            if (tid < MB) {
                int b = bbase + tid;
                xs[(p ^ 1) * MB + tid] =
                    (b < B_DIM && t + 1 < L_DIM) ? y[b * L_DIM + t + 1] : 0.f;
            }
        }
        cluster_sync();   // h1[p^1] + h2 visible cluster-wide

        // ---- stage C: layer-2 gates over h1[p^1] and h2 ----
        {
            const ulonglong2* hA = (const ulonglong2*)(h1s + (p ^ 1) * MB * 128);
            const ulonglong2* hB = (const ulonglong2*)h2s;
            #pragma unroll
            for (int half = 0; half < 2; ++half) {
                ull accA[8], accB[8];
                #pragma unroll
                for (int m = 0; m < 8; ++m) { accA[m] = 0ULL; accB[m] = 0ULL; }
                #pragma unroll
                for (int i = 0; i < 4; ++i) {
                    int k4 = (i << 3) + kq;
                    ulonglong2 wiA = Wsm[(32 + k4) * WSTRIDE + rl];
                    ulonglong2 wiB = Wsm[(32 + k4) * WSTRIDE + rB];
                    ulonglong2 whA = Wsm[(64 + k4) * WSTRIDE + rl];
                    ulonglong2 whB = Wsm[(64 + k4) * WSTRIDE + rB];
                    #pragma unroll
                    for (int m = 0; m < 8; ++m) {
                        ulonglong2 h1v = hA[((half << 3) + m) * 32 + k4];
                        ulonglong2 h2v = hB[((half << 3) + m) * 32 + k4];
                        ffma2(accA[m], wiA.x, h1v.x); ffma2(accA[m], wiA.y, h1v.y);
                        ffma2(accA[m], whA.x, h2v.x); ffma2(accA[m], whA.y, h2v.y);
                        ffma2(accB[m], wiB.x, h1v.x); ffma2(accB[m], wiB.y, h1v.y);
                        ffma2(accB[m], whB.x, h2v.x); ffma2(accB[m], whB.y, h2v.y);
                    }
                }
                #pragma unroll
                for (int m = 0; m < 8; ++m) {
                    int mm = (half << 3) + m;
                    float sA = pksum(accA[m]);
                    float sB = pksum(accB[m]);
                    sA += __shfl_xor_sync(0xffffffffu, sA, 1);
                    sA += __shfl_xor_sync(0xffffffffu, sA, 2);
                    sA += __shfl_xor_sync(0xffffffffu, sA, 4);
                    sB += __shfl_xor_sync(0xffffffffu, sB, 1);
                    sB += __shfl_xor_sync(0xffffffffu, sB, 2);
                    sB += __shfl_xor_sync(0xffffffffu, sB, 4);
                    if (kq == 0) {
                        gsm[mm * 128 + rl] = sA + b2A;
                        gsm[mm * 128 + rB] = sB + b2B;
                    }
                }
            }
        }
        __syncthreads();

        // ---- stage D: layer-2 cell update + output partial ----
        {
            const float* g = gsm + (m_c << 7);
            float ii = sigf(g[d_c]);
            float ff = sigf(g[32 + d_c]);
            float gg = tanh_fast(g[64 + d_c]);
            float oo = sigf(g[96 + d_c]);
            c2 = ff * c2 + ii * gg;
            h2n = oo * tanh_fast(c2);       // published at next step's phase 0
            float op = h2n * wlin_d;
            #pragma unroll
            for (int off = 16; off > 0; off >>= 1)
                op += __shfl_xor_sync(0xffffffffu, op, off);
            if (d_c == 0)
                push_rank0(op_u32 + ((((int)rank) * MB + m_c) << 2), op);
        }
        cluster_sync();   // outp visible on rank 0; buffers safe to rotate

        // ---- stage E: rank-0 writes the scalar outputs ----
        if (rank == 0 && tid < MB) {
            int b = bbase + tid;
            if (b < B_DIM)
                out[b * L_DIM + t] = outp[tid] + outp[MB + tid] +
                                     outp[2 * MB + tid] + outp[3 * MB + tid] + blin0;
        }
        p ^= 1;
    }
}

extern "C" void kernel_launch(void* const* d_in, const int* in_sizes, int n_in,
                              void* d_out, int out_size) {
    const float* y    = (const float*)d_in[0];
    const float* Wih1 = (const float*)d_in[1];
    const float* Whh1 = (const float*)d_in[2];
    const float* bih1 = (const float*)d_in[3];
    const float* bhh1 = (const float*)d_in[4];
    const float* Wih2 = (const float*)d_in[5];
    const float* Whh2 = (const float*)d_in[6];
    const float* bih2 = (const float*)d_in[7];
    const float* bhh2 = (const float*)d_in[8];
    const float* Wlin = (const float*)d_in[9];
    const float* blin = (const float*)d_in[10];
    float* out = (float*)d_out;

    cudaFuncSetAttribute(lstm_main, cudaFuncAttributeMaxDynamicSharedMemorySize,
                         SMEM_BYTES);

    pack_weights<<<(4 * 96 * 128 + 255) / 256, 256>>>(Whh1, Wih2, Whh2);
    lstm_main<<<NBLK, BLK_T, SMEM_BYTES>>>(y, Wih1, bih1, bhh1, bih2, bhh2,
                                           Wlin, blin, out);
}